// round 14
// baseline (speedup 1.0000x reference)
#include <cuda_runtime.h>
#include <cuda_fp16.h>
#include <cstdint>
#include <math.h>

#define KKER 10
#define TB   128
#define NT   256

// prepped-weight layout (halves): per k: net0(20992) net1(20992) net2(29184)
#define NOFF 20992
#define KSTR 71168
__device__ __half g_wtile[711680];
__device__ __half g_stile[16777216];   // 512 blk x 4 chunks x 8192
__device__ __half g_atile[8388608];    // 512 blk x 2 chunks x 8192

// smem byte offsets
#define XA_B  0u       // 2 x 16384
#define WT_B  32768u   // 2 x 8192
#define H_B   49152u   // 16384
#define W3_B  65536u   // 1024
#define BS_B  66560u   // 512 (128 floats)
#define OB_B  67072u   // 128 x 10 floats = 5120
#define SMEMB 72192u   // -> 2 CTAs/SM

__device__ __forceinline__ float sigf(float x) { return 1.0f / (1.0f + __expf(-x)); }
__device__ __forceinline__ uint32_t smem_u32(const void* p) {
    uint32_t a;
    asm("{ .reg .u64 t; cvta.to.shared.u64 t, %1; cvt.u32.u64 %0, t; }" : "=r"(a) : "l"(p));
    return a;
}
#define CPA16(dst, src) \
    asm volatile("cp.async.ca.shared.global [%0], [%1], 16;" :: "r"(dst), "l"(src))
#define CPA_COMMIT() asm volatile("cp.async.commit_group;" ::: "memory")
#define CPA_WAIT0()  asm volatile("cp.async.wait_group 0;" ::: "memory")

__device__ __forceinline__ void mma16(float c[4], uint32_t a0, uint32_t a1,
                                      uint32_t a2, uint32_t a3, uint32_t b0, uint32_t b1) {
    asm volatile("mma.sync.aligned.m16n8k16.row.col.f32.f16.f16.f32 "
                 "{%0,%1,%2,%3}, {%4,%5,%6,%7}, {%8,%9}, {%0,%1,%2,%3};"
                 : "+f"(c[0]), "+f"(c[1]), "+f"(c[2]), "+f"(c[3])
                 : "r"(a0), "r"(a1), "r"(a2), "r"(a3), "r"(b0), "r"(b1));
}

// ---------------- prep kernels ----------------
// k-permute within 16-group: half2 index pp -> col offset 2*(pp>>1) + 8*(pp&1)
__global__ void prep_x(const float* __restrict__ states, const float* __restrict__ actions) {
    int b = blockIdx.x;   // 512 blocks, 128 rows each
    const float* ss = states + (size_t)b * 128 * 256;
    __half2* sd = reinterpret_cast<__half2*>(g_stile + ((size_t)b << 15));
    for (int i = threadIdx.x; i < 16384; i += 256) {
        int j = i >> 12, rem = i & 4095;
        int q = rem >> 10, rr = rem & 1023, r = rr >> 3, pp = rr & 7;
        int c = (j << 6) + (q << 4) + ((pp >> 1) << 1) + ((pp & 1) << 3);
        sd[i] = __floats2half2_rn(ss[r * 256 + c], ss[r * 256 + c + 1]);
    }
    const float* as = actions + (size_t)b * 128 * 128;
    __half2* ad = reinterpret_cast<__half2*>(g_atile + ((size_t)b << 14));
    for (int i = threadIdx.x; i < 8192; i += 256) {
        int j = i >> 12, rem = i & 4095;
        int q = rem >> 10, rr = rem & 1023, r = rr >> 3, pp = rr & 7;
        int c = (j << 6) + (q << 4) + ((pp >> 1) << 1) + ((pp & 1) << 3);
        ad[i] = __floats2half2_rn(as[r * 128 + c], as[r * 128 + c + 1]);
    }
}

__global__ void prep_w(const float* __restrict__ kW1, const float* __restrict__ kW2,
                       const float* __restrict__ kW3,
                       const float* __restrict__ aW1, const float* __restrict__ aW2,
                       const float* __restrict__ aW3,
                       const float* __restrict__ cW1, const float* __restrict__ cW2,
                       const float* __restrict__ cW3)
{
    int k = blockIdx.x / 3, net = blockIdx.x % 3;
    const float* W1 = (net == 0) ? kW1 : ((net == 1) ? aW1 : cW1);
    const float* W2 = (net == 0) ? kW2 : ((net == 1) ? aW2 : cW2);
    const float* W3 = (net == 0) ? kW3 : ((net == 1) ? aW3 : cW3);
    const int IN = (net == 2) ? 384 : 256;
    __half2* dst = reinterpret_cast<__half2*>(g_wtile + (size_t)k * KSTR + (size_t)net * NOFF);
    const float* W1k = W1 + (size_t)k * IN * 64;
    int n1 = (IN * 64) >> 1;
    for (int i = threadIdx.x; i < n1; i += blockDim.x) {
        int j = i >> 11, rem = i & 2047;
        int q = rem >> 9, rr = rem & 511, o = rr >> 3, pp = rr & 7;
        int c = (j << 6) + (q << 4) + ((pp >> 1) << 1) + ((pp & 1) << 3);
        dst[i] = __floats2half2_rn(W1k[o * IN + c], W1k[o * IN + c + 1]);
    }
    const float* W2k = W2 + (size_t)k * 4096;
    __half2* d2 = dst + n1;
    for (int i = threadIdx.x; i < 2048; i += blockDim.x) {
        int q = i >> 9, rr = i & 511, o = rr >> 3, pp = rr & 7;
        int c = (q << 4) + ((pp >> 1) << 1) + ((pp & 1) << 3);
        d2[i] = __floats2half2_rn(W2k[o * 64 + c], W2k[o * 64 + c + 1]);
    }
    __half2* d3 = d2 + 2048;
    for (int i = threadIdx.x; i < 256; i += blockDim.x) {
        int q = i >> 6, rem = i & 63, o = rem >> 3, pp = rem & 7;
        int c = (q << 4) + ((pp >> 1) << 1) + ((pp & 1) << 3);
        float v0, v1;
        if (net == 0) { v0 = (o == 0) ? W3[(size_t)k * 64 + c] : 0.f;
                        v1 = (o == 0) ? W3[(size_t)k * 64 + c + 1] : 0.f; }
        else          { v0 = W3[(size_t)k * 512 + o * 64 + c];
                        v1 = W3[(size_t)k * 512 + o * 64 + c + 1]; }
        d3[i] = __floats2half2_rn(v0, v1);
    }
}

// ---------------- main ----------------
__device__ __forceinline__ void cp_w(uint32_t dstb, const __half* __restrict__ src, int tid) {
    #pragma unroll
    for (int q = 0; q < 2; q++) {
        int f = tid + 256 * q;
        CPA16(dstb + (uint32_t)(f << 4), src + (f << 3));
    }
}
__device__ __forceinline__ void cp_x(uint32_t dstb, const __half* __restrict__ src, int tid) {
    #pragma unroll
    for (int q = 0; q < 4; q++) {
        int f = tid + 256 * q;
        CPA16(dstb + (uint32_t)(f << 4), src + (f << 3));
    }
}

// warp m32 x n32 over one k64 chunk. A: [4q][128r][16], B: [4q][64n][16]
__device__ __forceinline__ void mma_chunk(const __half* __restrict__ A,
                                          const __half* __restrict__ B,
                                          float acc[2][4][4], int wbase, int nc0, int g, int t) {
    #pragma unroll
    for (int q = 0; q < 4; q++) {
        const __half* aq = A + (q << 11);
        const __half* bq = B + (q << 10);
        uint2 A00 = *reinterpret_cast<const uint2*>(aq + ((wbase + g) << 4) + 4 * t);
        uint2 A01 = *reinterpret_cast<const uint2*>(aq + ((wbase + g + 8) << 4) + 4 * t);
        uint2 A10 = *reinterpret_cast<const uint2*>(aq + ((wbase + g + 16) << 4) + 4 * t);
        uint2 A11 = *reinterpret_cast<const uint2*>(aq + ((wbase + g + 24) << 4) + 4 * t);
        #pragma unroll
        for (int nt = 0; nt < 4; nt++) {
            uint2 Bv = *reinterpret_cast<const uint2*>(bq + ((nc0 + nt * 8 + g) << 4) + 4 * t);
            mma16(acc[0][nt], A00.x, A01.x, A00.y, A01.y, Bv.x, Bv.y);
            mma16(acc[1][nt], A10.x, A11.x, A10.y, A11.y, Bv.x, Bv.y);
        }
    }
}
__device__ __forceinline__ void zacc(float acc[2][4][4]) {
    #pragma unroll
    for (int m = 0; m < 2; m++)
        #pragma unroll
        for (int n = 0; n < 4; n++)
            #pragma unroll
            for (int i = 0; i < 4; i++) acc[m][n][i] = 0.0f;
}
__device__ __forceinline__ void epi_h(const float acc[2][4][4], __half* __restrict__ h,
                                      const float* __restrict__ bias,
                                      int wbase, int nh, int g, int t) {
    #pragma unroll
    for (int nt = 0; nt < 4; nt++) {
        int nc = nh * 32 + nt * 8 + 2 * t;
        int q = (nh * 32 + nt * 8) >> 4;
        int po = 4 * t + 2 * (nt & 1);
        float b0 = bias[nc], b1 = bias[nc + 1];
        #pragma unroll
        for (int mt = 0; mt < 2; mt++) {
            int r0 = wbase + 16 * mt + g;
            __half2 v0 = __floats2half2_rn(fmaxf(acc[mt][nt][0] + b0, 0.f),
                                           fmaxf(acc[mt][nt][1] + b1, 0.f));
            __half2 v1 = __floats2half2_rn(fmaxf(acc[mt][nt][2] + b0, 0.f),
                                           fmaxf(acc[mt][nt][3] + b1, 0.f));
            *reinterpret_cast<__half2*>(h + (q << 11) + (r0 << 4) + po) = v0;
            *reinterpret_cast<__half2*>(h + (q << 11) + ((r0 + 8) << 4) + po) = v1;
        }
    }
}

__global__ void __launch_bounds__(NT, 2)
qplex_fp16b_kernel(
    const float* __restrict__ kb1, const float* __restrict__ kb2, const float* __restrict__ kb3,
    const float* __restrict__ ab1, const float* __restrict__ ab2, const float* __restrict__ ab3,
    const float* __restrict__ cb1, const float* __restrict__ cb2, const float* __restrict__ cb3,
    float* __restrict__ out)
{
    extern __shared__ char smc[];
    __half* xa[2] = {reinterpret_cast<__half*>(smc + XA_B),
                     reinterpret_cast<__half*>(smc + XA_B + 16384)};
    __half* wt[2] = {reinterpret_cast<__half*>(smc + WT_B),
                     reinterpret_cast<__half*>(smc + WT_B + 8192)};
    __half* h   = reinterpret_cast<__half*>(smc + H_B);
    __half* w3t = reinterpret_cast<__half*>(smc + W3_B);
    float* bs   = reinterpret_cast<float*>(smc + BS_B);
    float* ob   = reinterpret_cast<float*>(smc + OB_B);
    const uint32_t smb = smem_u32(smc);
    const uint32_t xab[2] = {smb + XA_B, smb + XA_B + 16384};
    const uint32_t wtb[2] = {smb + WT_B, smb + WT_B + 8192};
    const uint32_t w3b = smb + W3_B;

    const int tid = threadIdx.x, lane = tid & 31;
    const int g = lane >> 2, t = lane & 3;
    const int wid = tid >> 5, nh = wid >> 2, rg = wid & 3;
    const int wbase = rg << 5, nc0 = nh << 5;
    const int blk = blockIdx.x;

    const float* B1s[3] = {kb1, ab1, cb1};
    const float* B2s[3] = {kb2, ab2, cb2};
    const __half* xt = g_stile + ((size_t)blk << 15);
    const __half* at = g_atile + ((size_t)blk << 14);

    float acc[2][4][4], keyr = 0.f, agr[8], accr[8];
    #pragma unroll
    for (int o = 0; o < 8; o++) { accr[o] = 0.f; agr[o] = 0.f; }

    for (int k = 0; k < KKER; k++) {
        for (int net = 0; net < 3; net++) {
            const __half* wnet = g_wtile + (size_t)k * KSTR + (size_t)net * NOFF;
            const int NCH = (net == 2) ? 6 : 4;
            const __half* w2s = wnet + (size_t)NCH * 4096;
            const __half* w3s = w2s + 4096;

            cp_w(wtb[0], wnet, tid);
            cp_x(xab[0], xt, tid);
            CPA_COMMIT();
            if (tid < 64) {
                bs[tid]      = __ldg(B1s[net] + k * 64 + tid);
                bs[64 + tid] = __ldg(B2s[net] + k * 64 + tid);
            }
            zacc(acc);

            // ---- layer 1: NCH k64 chunks ----
            for (int j = 0; j < NCH; j++) {
                CPA_WAIT0();
                __syncthreads();
                if (j + 1 < NCH) {
                    const __half* xsrc = (j + 1 < 4) ? xt + ((size_t)(j + 1) << 13)
                                                     : at + ((size_t)(j - 3) << 13);
                    cp_w(wtb[(j + 1) & 1], wnet + ((size_t)(j + 1) << 12), tid);
                    cp_x(xab[(j + 1) & 1], xsrc, tid);
                } else {
                    cp_w(wtb[(j + 1) & 1], w2s, tid);
                    if (tid < 64) CPA16(w3b + (uint32_t)(tid << 4), w3s + (tid << 3));
                }
                CPA_COMMIT();
                mma_chunk(xa[j & 1], wt[j & 1], acc, wbase, nc0, g, t);
            }
            epi_h(acc, h, bs, wbase, nh, g, t);
            zacc(acc);

            // ---- layer 2 (single k64 chunk; A = h) ----
            CPA_WAIT0();
            __syncthreads();
            mma_chunk(h, wt[NCH & 1], acc, wbase, nc0, g, t);
            asm volatile("bar.sync %0, %1;" :: "r"(rg + 1), "r"(64) : "memory");
            epi_h(acc, h, bs + 64, wbase, nh, g, t);
            zacc(acc);
            asm volatile("bar.sync %0, %1;" :: "r"(rg + 1), "r"(64) : "memory");

            // ---- layer 3 (m32 x n8, nh==0 warps cover all 128 rows) ----
            if (nh == 0) {
                float a3[2][4];
                #pragma unroll
                for (int m = 0; m < 2; m++)
                    #pragma unroll
                    for (int i = 0; i < 4; i++) a3[m][i] = 0.f;
                #pragma unroll
                for (int q = 0; q < 4; q++) {
                    const __half* aq = h + (q << 11);
                    uint2 A00 = *reinterpret_cast<const uint2*>(aq + ((wbase + g) << 4) + 4 * t);
                    uint2 A01 = *reinterpret_cast<const uint2*>(aq + ((wbase + g + 8) << 4) + 4 * t);
                    uint2 A10 = *reinterpret_cast<const uint2*>(aq + ((wbase + g + 16) << 4) + 4 * t);
                    uint2 A11 = *reinterpret_cast<const uint2*>(aq + ((wbase + g + 24) << 4) + 4 * t);
                    uint2 Bv = *reinterpret_cast<const uint2*>(w3t + (q << 7) + (g << 4) + 4 * t);
                    mma16(a3[0], A00.x, A01.x, A00.y, A01.y, Bv.x, Bv.y);
                    mma16(a3[1], A10.x, A11.x, A10.y, A11.y, Bv.x, Bv.y);
                }
                #pragma unroll
                for (int mt = 0; mt < 2; mt++) {
                    int r0 = wbase + 16 * mt + g;
                    *reinterpret_cast<float2*>(ob + r0 * 10 + 2 * t)       = make_float2(a3[mt][0], a3[mt][1]);
                    *reinterpret_cast<float2*>(ob + (r0 + 8) * 10 + 2 * t) = make_float2(a3[mt][2], a3[mt][3]);
                }
            }
            __syncthreads();
            if (tid < 128) {
                const float* orow = ob + tid * 10;
                if (net == 0) {
                    keyr = fabsf(orow[0] + __ldg(kb3 + k)) + 1e-10f;
                } else if (net == 1) {
                    #pragma unroll
                    for (int o = 0; o < 8; o++)
                        agr[o] = sigf(orow[o] + __ldg(ab3 + k * 8 + o));
                } else {
                    #pragma unroll
                    for (int o = 0; o < 8; o++)
                        accr[o] += keyr * agr[o] * sigf(orow[o] + __ldg(cb3 + k * 8 + o));
                }
            }
        }
    }

    if (tid < 128) {
        float4* op = reinterpret_cast<float4*>(out + (size_t)(blk * TB + tid) * 8);
        op[0] = make_float4(accr[0], accr[1], accr[2], accr[3]);
        op[1] = make_float4(accr[4], accr[5], accr[6], accr[7]);
    }
}

extern "C" void kernel_launch(void* const* d_in, const int* in_sizes, int n_in,
                              void* d_out, int out_size)
{
    const float* states  = (const float*)d_in[0];
    const float* actions = (const float*)d_in[1];
    const float* kW1 = (const float*)d_in[2];  const float* kb1 = (const float*)d_in[3];
    const float* kW2 = (const float*)d_in[4];  const float* kb2 = (const float*)d_in[5];
    const float* kW3 = (const float*)d_in[6];  const float* kb3 = (const float*)d_in[7];
    const float* aW1 = (const float*)d_in[8];  const float* ab1 = (const float*)d_in[9];
    const float* aW2 = (const float*)d_in[10]; const float* ab2 = (const float*)d_in[11];
    const float* aW3 = (const float*)d_in[12]; const float* ab3 = (const float*)d_in[13];
    const float* cW1 = (const float*)d_in[14]; const float* cb1 = (const float*)d_in[15];
    const float* cW2 = (const float*)d_in[16]; const float* cb2 = (const float*)d_in[17];
    const float* cW3 = (const float*)d_in[18]; const float* cb3 = (const float*)d_in[19];
    float* out = (float*)d_out;

    prep_w<<<30, 256>>>(kW1, kW2, kW3, aW1, aW2, aW3, cW1, cW2, cW3);
    prep_x<<<512, 256>>>(states, actions);

    cudaFuncSetAttribute(qplex_fp16b_kernel,
                         cudaFuncAttributeMaxDynamicSharedMemorySize, (int)SMEMB);
    qplex_fp16b_kernel<<<512, NT, SMEMB>>>(
        kb1, kb2, kb3, ab1, ab2, ab3, cb1, cb2, cb3, out);
}

// round 15
// speedup vs baseline: 1.0621x; 1.0621x over previous
#include <cuda_runtime.h>
#include <cuda_fp16.h>
#include <cstdint>
#include <math.h>

#define KKER 10
#define TB   128
#define NT   128

// prepped-weight layout (halves): per k: net0(20992) net1(20992) net2(29184)
#define NOFF 20992
#define KSTR 71168
__device__ __half g_wtile[711680];
__device__ __half g_stile[16777216];   // 512 blk x 4 chunks x 8192
__device__ __half g_atile[8388608];    // 512 blk x 2 chunks x 8192

// smem byte offsets
#define XA_B  0u       // 2 x 16384
#define WT_B  32768u   // 2 x 8192
#define W3_B  49152u   // 1024
#define BS_B  50176u   // 2 ring slots x 512 (128 floats each)
#define OB_B  51200u   // 128 x 10 floats = 5120
#define SMEMB 56320u   // x4 CTAs = 225280 <= 228KB

__device__ __forceinline__ float sigf(float x) { return 1.0f / (1.0f + __expf(-x)); }
__device__ __forceinline__ uint32_t smem_u32(const void* p) {
    uint32_t a;
    asm("{ .reg .u64 t; cvta.to.shared.u64 t, %1; cvt.u32.u64 %0, t; }" : "=r"(a) : "l"(p));
    return a;
}
__device__ __forceinline__ uint32_t h2u(float x, float y) {
    __half2 h = __floats2half2_rn(x, y);
    return *reinterpret_cast<uint32_t*>(&h);
}
#define CPA16(dst, src) \
    asm volatile("cp.async.ca.shared.global [%0], [%1], 16;" :: "r"(dst), "l"(src))
#define CPA_COMMIT() asm volatile("cp.async.commit_group;" ::: "memory")
#define CPA_WAIT0()  asm volatile("cp.async.wait_group 0;" ::: "memory")

__device__ __forceinline__ void mma16(float c[4], uint32_t a0, uint32_t a1,
                                      uint32_t a2, uint32_t a3, uint32_t b0, uint32_t b1) {
    asm volatile("mma.sync.aligned.m16n8k16.row.col.f32.f16.f16.f32 "
                 "{%0,%1,%2,%3}, {%4,%5,%6,%7}, {%8,%9}, {%0,%1,%2,%3};"
                 : "+f"(c[0]), "+f"(c[1]), "+f"(c[2]), "+f"(c[3])
                 : "r"(a0), "r"(a1), "r"(a2), "r"(a3), "r"(b0), "r"(b1));
}

// ---------------- prep kernels (round-14 layouts, verified) ----------------
__global__ void prep_x(const float* __restrict__ states, const float* __restrict__ actions) {
    int b = blockIdx.x;   // 512 blocks, 128 rows
    const float* ss = states + (size_t)b * 128 * 256;
    __half2* sd = reinterpret_cast<__half2*>(g_stile + ((size_t)b << 15));
    for (int i = threadIdx.x; i < 16384; i += 256) {
        int j = i >> 12, rem = i & 4095;
        int q = rem >> 10, rr = rem & 1023, r = rr >> 3, pp = rr & 7;
        int c = (j << 6) + (q << 4) + ((pp >> 1) << 1) + ((pp & 1) << 3);
        sd[i] = __floats2half2_rn(ss[r * 256 + c], ss[r * 256 + c + 1]);
    }
    const float* as = actions + (size_t)b * 128 * 128;
    __half2* ad = reinterpret_cast<__half2*>(g_atile + ((size_t)b << 14));
    for (int i = threadIdx.x; i < 8192; i += 256) {
        int j = i >> 12, rem = i & 4095;
        int q = rem >> 10, rr = rem & 1023, r = rr >> 3, pp = rr & 7;
        int c = (j << 6) + (q << 4) + ((pp >> 1) << 1) + ((pp & 1) << 3);
        ad[i] = __floats2half2_rn(as[r * 128 + c], as[r * 128 + c + 1]);
    }
}

__global__ void prep_w(const float* __restrict__ kW1, const float* __restrict__ kW2,
                       const float* __restrict__ kW3,
                       const float* __restrict__ aW1, const float* __restrict__ aW2,
                       const float* __restrict__ aW3,
                       const float* __restrict__ cW1, const float* __restrict__ cW2,
                       const float* __restrict__ cW3)
{
    int k = blockIdx.x / 3, net = blockIdx.x % 3;
    const float* W1 = (net == 0) ? kW1 : ((net == 1) ? aW1 : cW1);
    const float* W2 = (net == 0) ? kW2 : ((net == 1) ? aW2 : cW2);
    const float* W3 = (net == 0) ? kW3 : ((net == 1) ? aW3 : cW3);
    const int IN = (net == 2) ? 384 : 256;
    __half2* dst = reinterpret_cast<__half2*>(g_wtile + (size_t)k * KSTR + (size_t)net * NOFF);
    const float* W1k = W1 + (size_t)k * IN * 64;
    int n1 = (IN * 64) >> 1;
    for (int i = threadIdx.x; i < n1; i += blockDim.x) {
        int j = i >> 11, rem = i & 2047;
        int q = rem >> 9, rr = rem & 511, o = rr >> 3, pp = rr & 7;
        int c = (j << 6) + (q << 4) + ((pp >> 1) << 1) + ((pp & 1) << 3);
        dst[i] = __floats2half2_rn(W1k[o * IN + c], W1k[o * IN + c + 1]);
    }
    const float* W2k = W2 + (size_t)k * 4096;
    __half2* d2 = dst + n1;
    for (int i = threadIdx.x; i < 2048; i += blockDim.x) {
        int q = i >> 9, rr = i & 511, o = rr >> 3, pp = rr & 7;
        int c = (q << 4) + ((pp >> 1) << 1) + ((pp & 1) << 3);
        d2[i] = __floats2half2_rn(W2k[o * 64 + c], W2k[o * 64 + c + 1]);
    }
    __half2* d3 = d2 + 2048;
    for (int i = threadIdx.x; i < 256; i += blockDim.x) {
        int q = i >> 6, rem = i & 63, o = rem >> 3, pp = rem & 7;
        int c = (q << 4) + ((pp >> 1) << 1) + ((pp & 1) << 3);
        float v0, v1;
        if (net == 0) { v0 = (o == 0) ? W3[(size_t)k * 64 + c] : 0.f;
                        v1 = (o == 0) ? W3[(size_t)k * 64 + c + 1] : 0.f; }
        else          { v0 = W3[(size_t)k * 512 + o * 64 + c];
                        v1 = W3[(size_t)k * 512 + o * 64 + c + 1]; }
        d3[i] = __floats2half2_rn(v0, v1);
    }
}

// ---------------- main ----------------
__device__ __forceinline__ void cp_w(uint32_t dstb, const __half* __restrict__ src, int tid) {
    #pragma unroll
    for (int q = 0; q < 4; q++) {
        int f = tid + 128 * q;
        CPA16(dstb + (uint32_t)(f << 4), src + (f << 3));
    }
}
__device__ __forceinline__ void cp_x(uint32_t dstb, const __half* __restrict__ src, int tid) {
    #pragma unroll
    for (int q = 0; q < 8; q++) {
        int f = tid + 128 * q;
        CPA16(dstb + (uint32_t)(f << 4), src + (f << 3));
    }
}

// warp m32 x n64 over one k64 chunk. A: [4q][128r][16], B: [4q][64n][16]
__device__ __forceinline__ void mma_l1(const __half* __restrict__ A,
                                       const __half* __restrict__ B,
                                       float acc[2][8][4], int wbase, int g, int t) {
    #pragma unroll
    for (int q = 0; q < 4; q++) {
        const __half* aq = A + (q << 11);
        const __half* bq = B + (q << 10);
        uint2 A00 = *reinterpret_cast<const uint2*>(aq + ((wbase + g) << 4) + 4 * t);
        uint2 A01 = *reinterpret_cast<const uint2*>(aq + ((wbase + g + 8) << 4) + 4 * t);
        uint2 A10 = *reinterpret_cast<const uint2*>(aq + ((wbase + g + 16) << 4) + 4 * t);
        uint2 A11 = *reinterpret_cast<const uint2*>(aq + ((wbase + g + 24) << 4) + 4 * t);
        #pragma unroll
        for (int nt = 0; nt < 8; nt++) {
            uint2 Bv = *reinterpret_cast<const uint2*>(bq + ((nt * 8 + g) << 4) + 4 * t);
            mma16(acc[0][nt], A00.x, A01.x, A00.y, A01.y, Bv.x, Bv.y);
            mma16(acc[1][nt], A10.x, A11.x, A10.y, A11.y, Bv.x, Bv.y);
        }
    }
}
__device__ __forceinline__ void zacc(float acc[2][8][4]) {
    #pragma unroll
    for (int m = 0; m < 2; m++)
        #pragma unroll
        for (int n = 0; n < 8; n++)
            #pragma unroll
            for (int i = 0; i < 4; i++) acc[m][n][i] = 0.0f;
}
// bias+relu+cvt: acc -> A-fragments for next layer (pure registers)
__device__ __forceinline__ void epi_frag(const float acc[2][8][4], uint32_t af[4][2][4],
                                         const float* __restrict__ bias, int t) {
    #pragma unroll
    for (int q = 0; q < 4; q++) {
        #pragma unroll
        for (int h = 0; h < 2; h++) {       // nt = 2q + h
            int nt = 2 * q + h;
            float b0 = bias[nt * 8 + 2 * t], b1 = bias[nt * 8 + 2 * t + 1];
            #pragma unroll
            for (int mt = 0; mt < 2; mt++) {
                af[q][mt][2 * h]     = h2u(fmaxf(acc[mt][nt][0] + b0, 0.f),
                                           fmaxf(acc[mt][nt][1] + b1, 0.f));
                af[q][mt][2 * h + 1] = h2u(fmaxf(acc[mt][nt][2] + b0, 0.f),
                                           fmaxf(acc[mt][nt][3] + b1, 0.f));
            }
        }
    }
}

__global__ void __launch_bounds__(NT, 4)
qplex_reg_kernel(
    const float* __restrict__ kb1, const float* __restrict__ kb2, const float* __restrict__ kb3,
    const float* __restrict__ ab1, const float* __restrict__ ab2, const float* __restrict__ ab3,
    const float* __restrict__ cb1, const float* __restrict__ cb2, const float* __restrict__ cb3,
    float* __restrict__ out)
{
    extern __shared__ char smc[];
    __half* xa[2] = {reinterpret_cast<__half*>(smc + XA_B),
                     reinterpret_cast<__half*>(smc + XA_B + 16384)};
    __half* wt[2] = {reinterpret_cast<__half*>(smc + WT_B),
                     reinterpret_cast<__half*>(smc + WT_B + 8192)};
    __half* w3t = reinterpret_cast<__half*>(smc + W3_B);
    float* bsr  = reinterpret_cast<float*>(smc + BS_B);    // 2 ring slots x 128
    float* ob   = reinterpret_cast<float*>(smc + OB_B);
    const uint32_t smb = smem_u32(smc);
    const uint32_t xab[2] = {smb + XA_B, smb + XA_B + 16384};
    const uint32_t wtb[2] = {smb + WT_B, smb + WT_B + 8192};
    const uint32_t w3b = smb + W3_B;

    const int tid = threadIdx.x, lane = tid & 31;
    const int g = lane >> 2, t = lane & 3;
    const int wid = tid >> 5;
    const int wbase = wid << 5;
    const int blk = blockIdx.x;

    const float* B1s[3] = {kb1, ab1, cb1};
    const float* B2s[3] = {kb2, ab2, cb2};
    const __half* xt = g_stile + ((size_t)blk << 15);
    const __half* at = g_atile + ((size_t)blk << 14);

    float acc[2][8][4];
    uint32_t af[4][2][4];
    float keyr = 0.f, agr[8], accr[8];
    #pragma unroll
    for (int o = 0; o < 8; o++) { accr[o] = 0.f; agr[o] = 0.f; }

    // prologue: chunk0 of (k=0,net=0)
    int p = 0;
    cp_w(wtb[0], g_wtile, tid);
    cp_x(xab[0], xt, tid);
    CPA_COMMIT();

    for (int it = 0; it < 30; it++) {
        const int k = it / 3, net = it % 3;
        const __half* wnet = g_wtile + (size_t)k * KSTR + (size_t)net * NOFF;
        const int NCH = (net == 2) ? 6 : 4;
        const __half* w2s = wnet + (size_t)NCH * 4096;
        const __half* w3s = w2s + 4096;
        float* bs = bsr + (it & 1) * 128;

        // biases into this net's ring slot (prior slot still readable by laggards)
        if (tid < 64) bs[tid] = __ldg(B1s[net] + k * 64 + tid);
        else          bs[64 + (tid - 64)] = __ldg(B2s[net] + k * 64 + (tid - 64));
        zacc(acc);

        // ---- layer 1: NCH k64 chunks ----
        for (int j = 0; j < NCH; j++) {
            CPA_WAIT0();
            __syncthreads();
            if (j + 1 < NCH) {
                const __half* xsrc = (j + 1 < 4) ? xt + ((size_t)(j + 1) << 13)
                                                 : at + ((size_t)(j - 3) << 13);
                cp_w(wtb[(p + j + 1) & 1], wnet + ((size_t)(j + 1) << 12), tid);
                cp_x(xab[(p + j + 1) & 1], xsrc, tid);
            } else {
                cp_w(wtb[(p + NCH) & 1], w2s, tid);
                if (tid < 64) CPA16(w3b + (uint32_t)(tid << 4), w3s + (tid << 3));
            }
            CPA_COMMIT();
            mma_l1(xa[(p + j) & 1], wt[(p + j) & 1], acc, wbase, g, t);
        }

        // ---- L2 barrier: W2 + w3 staged; all L1 reads done ----
        CPA_WAIT0();
        __syncthreads();
        if (it < 29) {   // prefetch next net chunk0 into free buffers
            const int knext = (it + 1) / 3, netnext = (it + 1) % 3;
            const __half* wnext = g_wtile + (size_t)knext * KSTR + (size_t)netnext * NOFF;
            cp_w(wtb[(p + NCH + 1) & 1], wnext, tid);
            cp_x(xab[(p + NCH + 1) & 1], xt, tid);
            CPA_COMMIT();
        }

        // ---- epi1 + layer 2 entirely in registers (A = converted acc) ----
        epi_frag(acc, af, bs, t);
        zacc(acc);
        {
            const __half* wtL2 = wt[(p + NCH) & 1];
            #pragma unroll
            for (int q = 0; q < 4; q++) {
                const __half* bq = wtL2 + (q << 10);
                #pragma unroll
                for (int nt = 0; nt < 8; nt++) {
                    uint2 Bv = *reinterpret_cast<const uint2*>(bq + ((nt * 8 + g) << 4) + 4 * t);
                    mma16(acc[0][nt], af[q][0][0], af[q][0][1], af[q][0][2], af[q][0][3], Bv.x, Bv.y);
                    mma16(acc[1][nt], af[q][1][0], af[q][1][1], af[q][1][2], af[q][1][3], Bv.x, Bv.y);
                }
            }
        }

        // ---- epi2 + layer 3 in registers ----
        epi_frag(acc, af, bs + 64, t);
        {
            float a3[2][4];
            #pragma unroll
            for (int m = 0; m < 2; m++)
                #pragma unroll
                for (int i = 0; i < 4; i++) a3[m][i] = 0.f;
            #pragma unroll
            for (int q = 0; q < 4; q++) {
                uint2 Bv = *reinterpret_cast<const uint2*>(w3t + (q << 7) + (g << 4) + 4 * t);
                mma16(a3[0], af[q][0][0], af[q][0][1], af[q][0][2], af[q][0][3], Bv.x, Bv.y);
                mma16(a3[1], af[q][1][0], af[q][1][1], af[q][1][2], af[q][1][3], Bv.x, Bv.y);
            }
            #pragma unroll
            for (int mt = 0; mt < 2; mt++) {
                int r0 = wbase + 16 * mt + g;
                *reinterpret_cast<float2*>(ob + r0 * 10 + 2 * t)       = make_float2(a3[mt][0], a3[mt][1]);
                *reinterpret_cast<float2*>(ob + (r0 + 8) * 10 + 2 * t) = make_float2(a3[mt][2], a3[mt][3]);
            }
        }
        __syncwarp();
        // ---- combine (warp-local: row tid belongs to warp tid>>5) ----
        {
            const float* orow = ob + tid * 10;
            if (net == 0) {
                keyr = fabsf(orow[0] + __ldg(kb3 + k)) + 1e-10f;
            } else if (net == 1) {
                #pragma unroll
                for (int o = 0; o < 8; o++)
                    agr[o] = sigf(orow[o] + __ldg(ab3 + k * 8 + o));
            } else {
                #pragma unroll
                for (int o = 0; o < 8; o++)
                    accr[o] += keyr * agr[o] * sigf(orow[o] + __ldg(cb3 + k * 8 + o));
            }
        }
        __syncwarp();
        p = (p + NCH + 1) & 1;
    }

    float4* op = reinterpret_cast<float4*>(out + (size_t)(blk * TB + tid) * 8);
    op[0] = make_float4(accr[0], accr[1], accr[2], accr[3]);
    op[1] = make_float4(accr[4], accr[5], accr[6], accr[7]);
}

extern "C" void kernel_launch(void* const* d_in, const int* in_sizes, int n_in,
                              void* d_out, int out_size)
{
    const float* states  = (const float*)d_in[0];
    const float* actions = (const float*)d_in[1];
    const float* kW1 = (const float*)d_in[2];  const float* kb1 = (const float*)d_in[3];
    const float* kW2 = (const float*)d_in[4];  const float* kb2 = (const float*)d_in[5];
    const float* kW3 = (const float*)d_in[6];  const float* kb3 = (const float*)d_in[7];
    const float* aW1 = (const float*)d_in[8];  const float* ab1 = (const float*)d_in[9];
    const float* aW2 = (const float*)d_in[10]; const float* ab2 = (const float*)d_in[11];
    const float* aW3 = (const float*)d_in[12]; const float* ab3 = (const float*)d_in[13];
    const float* cW1 = (const float*)d_in[14]; const float* cb1 = (const float*)d_in[15];
    const float* cW2 = (const float*)d_in[16]; const float* cb2 = (const float*)d_in[17];
    const float* cW3 = (const float*)d_in[18]; const float* cb3 = (const float*)d_in[19];
    float* out = (float*)d_out;

    prep_w<<<30, 256>>>(kW1, kW2, kW3, aW1, aW2, aW3, cW1, cW2, cW3);
    prep_x<<<512, 256>>>(states, actions);

    cudaFuncSetAttribute(qplex_reg_kernel,
                         cudaFuncAttributeMaxDynamicSharedMemorySize, (int)SMEMB);
    qplex_reg_kernel<<<512, NT, SMEMB>>>(
        kb1, kb2, kb3, ab1, ab2, ab3, cb1, cb2, cb3, out);
}

// round 16
// speedup vs baseline: 1.1697x; 1.1013x over previous
#include <cuda_runtime.h>
#include <cuda_fp16.h>
#include <cstdint>
#include <math.h>

#define KKER 10
#define TB   64
#define NT   128

// prepped-weight layout (halves): per k: net0(20992) net1(20992) net2(29184)
#define NOFF 20992
#define KSTR 71168
__device__ __half g_wtile[711680];
__device__ __half g_stile[16777216];   // 1024 x 4 chunks x 4096
__device__ __half g_atile[8388608];    // 1024 x 2 chunks x 4096

// smem byte offsets
#define XA_B  0u       // 2 x 8192
#define WT_B  16384u   // 2 x 8192
#define H_B   32768u   // 8192
#define W3_B  40960u   // 1024
#define BS_B  41984u   // 512 (128 floats)
#define OB_B  42496u   // 2560 (64 x 10 floats)
#define SMEMB 45056u   // +1KB reserved -> 5 CTAs/SM (230400 <= 233472)

__device__ __forceinline__ float sigf(float x) { return 1.0f / (1.0f + __expf(-x)); }
__device__ __forceinline__ uint32_t smem_u32(const void* p) {
    uint32_t a;
    asm("{ .reg .u64 t; cvta.to.shared.u64 t, %1; cvt.u32.u64 %0, t; }" : "=r"(a) : "l"(p));
    return a;
}
#define CPA16(dst, src) \
    asm volatile("cp.async.ca.shared.global [%0], [%1], 16;" :: "r"(dst), "l"(src))
#define CPA_COMMIT() asm volatile("cp.async.commit_group;" ::: "memory")
#define CPA_WAIT0()  asm volatile("cp.async.wait_group 0;" ::: "memory")

__device__ __forceinline__ void mma16(float c[4], uint32_t a0, uint32_t a1,
                                      uint32_t a2, uint32_t a3, uint32_t b0, uint32_t b1) {
    asm volatile("mma.sync.aligned.m16n8k16.row.col.f32.f16.f16.f32 "
                 "{%0,%1,%2,%3}, {%4,%5,%6,%7}, {%8,%9}, {%0,%1,%2,%3};"
                 : "+f"(c[0]), "+f"(c[1]), "+f"(c[2]), "+f"(c[3])
                 : "r"(a0), "r"(a1), "r"(a2), "r"(a3), "r"(b0), "r"(b1));
}

// ---------------- fused prep kernel ----------------
// blocks [0,1024): x tiles; blocks [1024,1144): weights, 4-way split per (k,net)
__global__ void prep_all(const float* __restrict__ states, const float* __restrict__ actions,
                         const float* __restrict__ kW1, const float* __restrict__ kW2,
                         const float* __restrict__ kW3,
                         const float* __restrict__ aW1, const float* __restrict__ aW2,
                         const float* __restrict__ aW3,
                         const float* __restrict__ cW1, const float* __restrict__ cW2,
                         const float* __restrict__ cW3)
{
    int b = blockIdx.x;
    if (b < 1024) {
        const float* ss = states + (size_t)b * 64 * 256;
        __half2* sd = reinterpret_cast<__half2*>(g_stile + ((size_t)b << 14));
        for (int i = threadIdx.x; i < 8192; i += 256) {
            int j = i >> 11, rem = i & 2047;
            int q = rem >> 9, rr = rem & 511, r = rr >> 3, pp = rr & 7;
            int c = (j << 6) + (q << 4) + ((pp >> 1) << 1) + ((pp & 1) << 3);
            sd[i] = __floats2half2_rn(ss[r * 256 + c], ss[r * 256 + c + 1]);
        }
        const float* as = actions + (size_t)b * 64 * 128;
        __half2* ad = reinterpret_cast<__half2*>(g_atile + ((size_t)b << 13));
        for (int i = threadIdx.x; i < 4096; i += 256) {
            int j = i >> 11, rem = i & 2047;
            int q = rem >> 9, rr = rem & 511, r = rr >> 3, pp = rr & 7;
            int c = (j << 6) + (q << 4) + ((pp >> 1) << 1) + ((pp & 1) << 3);
            ad[i] = __floats2half2_rn(as[r * 128 + c], as[r * 128 + c + 1]);
        }
        return;
    }
    int u = (b - 1024) >> 2, q4 = (b - 1024) & 3;
    int k = u / 3, net = u % 3;
    const float* W1 = (net == 0) ? kW1 : ((net == 1) ? aW1 : cW1);
    const float* W2 = (net == 0) ? kW2 : ((net == 1) ? aW2 : cW2);
    const float* W3 = (net == 0) ? kW3 : ((net == 1) ? aW3 : cW3);
    const int IN = (net == 2) ? 384 : 256;
    __half2* dst = reinterpret_cast<__half2*>(g_wtile + (size_t)k * KSTR + (size_t)net * NOFF);
    const float* W1k = W1 + (size_t)k * IN * 64;
    int n1 = (IN * 64) >> 1;
    for (int i = threadIdx.x + (q4 << 8); i < n1; i += 1024) {
        int j = i >> 11, rem = i & 2047;
        int q = rem >> 9, rr = rem & 511, o = rr >> 3, pp = rr & 7;
        int c = (j << 6) + (q << 4) + ((pp >> 1) << 1) + ((pp & 1) << 3);
        dst[i] = __floats2half2_rn(W1k[o * IN + c], W1k[o * IN + c + 1]);
    }
    const float* W2k = W2 + (size_t)k * 4096;
    __half2* d2 = dst + n1;
    for (int i = threadIdx.x + (q4 << 8); i < 2048; i += 1024) {
        int q = i >> 9, rr = i & 511, o = rr >> 3, pp = rr & 7;
        int c = (q << 4) + ((pp >> 1) << 1) + ((pp & 1) << 3);
        d2[i] = __floats2half2_rn(W2k[o * 64 + c], W2k[o * 64 + c + 1]);
    }
    __half2* d3 = d2 + 2048;
    for (int i = threadIdx.x + (q4 << 8); i < 256; i += 1024) {
        int q = i >> 6, rem = i & 63, o = rem >> 3, pp = rem & 7;
        int c = (q << 4) + ((pp >> 1) << 1) + ((pp & 1) << 3);
        float v0, v1;
        if (net == 0) { v0 = (o == 0) ? W3[(size_t)k * 64 + c] : 0.f;
                        v1 = (o == 0) ? W3[(size_t)k * 64 + c + 1] : 0.f; }
        else          { v0 = W3[(size_t)k * 512 + o * 64 + c];
                        v1 = W3[(size_t)k * 512 + o * 64 + c + 1]; }
        d3[i] = __floats2half2_rn(v0, v1);
    }
}

// ---------------- main ----------------
__device__ __forceinline__ void cp_chunk(uint32_t dstb, const __half* __restrict__ src, int tid) {
    #pragma unroll
    for (int q = 0; q < 4; q++) {
        int f = tid + 128 * q;
        CPA16(dstb + (uint32_t)(f << 4), src + (f << 3));
    }
}
__device__ __forceinline__ void mma_chunk(const __half* __restrict__ A,
                                          const __half* __restrict__ B,
                                          float acc[2][4][4], int wbase, int nc0, int g, int t) {
    #pragma unroll
    for (int q = 0; q < 4; q++) {
        const __half* aq = A + (q << 10);
        const __half* bq = B + (q << 10);
        uint2 A00 = *reinterpret_cast<const uint2*>(aq + ((wbase + g) << 4) + 4 * t);
        uint2 A01 = *reinterpret_cast<const uint2*>(aq + ((wbase + g + 8) << 4) + 4 * t);
        uint2 A10 = *reinterpret_cast<const uint2*>(aq + ((wbase + g + 16) << 4) + 4 * t);
        uint2 A11 = *reinterpret_cast<const uint2*>(aq + ((wbase + g + 24) << 4) + 4 * t);
        #pragma unroll
        for (int nt = 0; nt < 4; nt++) {
            uint2 Bv = *reinterpret_cast<const uint2*>(bq + ((nc0 + nt * 8 + g) << 4) + 4 * t);
            mma16(acc[0][nt], A00.x, A01.x, A00.y, A01.y, Bv.x, Bv.y);
            mma16(acc[1][nt], A10.x, A11.x, A10.y, A11.y, Bv.x, Bv.y);
        }
    }
}
__device__ __forceinline__ void zacc(float acc[2][4][4]) {
    #pragma unroll
    for (int m = 0; m < 2; m++)
        #pragma unroll
        for (int n = 0; n < 4; n++)
            #pragma unroll
            for (int i = 0; i < 4; i++) acc[m][n][i] = 0.0f;
}
__device__ __forceinline__ void epi_h(const float acc[2][4][4], __half* __restrict__ h,
                                      const float* __restrict__ bias,
                                      int wbase, int nh, int g, int t) {
    #pragma unroll
    for (int nt = 0; nt < 4; nt++) {
        int nc = nh * 32 + nt * 8 + 2 * t;
        int q = (nh * 32 + nt * 8) >> 4;
        int po = 4 * t + 2 * (nt & 1);
        float b0 = bias[nc], b1 = bias[nc + 1];
        #pragma unroll
        for (int mt = 0; mt < 2; mt++) {
            int r0 = wbase + 16 * mt + g;
            __half2 v0 = __floats2half2_rn(fmaxf(acc[mt][nt][0] + b0, 0.f),
                                           fmaxf(acc[mt][nt][1] + b1, 0.f));
            __half2 v1 = __floats2half2_rn(fmaxf(acc[mt][nt][2] + b0, 0.f),
                                           fmaxf(acc[mt][nt][3] + b1, 0.f));
            *reinterpret_cast<__half2*>(h + (q << 10) + (r0 << 4) + po) = v0;
            *reinterpret_cast<__half2*>(h + (q << 10) + ((r0 + 8) << 4) + po) = v1;
        }
    }
}

__global__ void __launch_bounds__(NT, 5)
qplex_occ5_kernel(
    const float* __restrict__ kb1, const float* __restrict__ kb2, const float* __restrict__ kb3,
    const float* __restrict__ ab1, const float* __restrict__ ab2, const float* __restrict__ ab3,
    const float* __restrict__ cb1, const float* __restrict__ cb2, const float* __restrict__ cb3,
    float* __restrict__ out)
{
    extern __shared__ char smc[];
    __half* xa[2] = {reinterpret_cast<__half*>(smc + XA_B),
                     reinterpret_cast<__half*>(smc + XA_B + 8192)};
    __half* wt[2] = {reinterpret_cast<__half*>(smc + WT_B),
                     reinterpret_cast<__half*>(smc + WT_B + 8192)};
    __half* h   = reinterpret_cast<__half*>(smc + H_B);
    __half* w3t = reinterpret_cast<__half*>(smc + W3_B);
    float* bs   = reinterpret_cast<float*>(smc + BS_B);
    float* ob   = reinterpret_cast<float*>(smc + OB_B);
    const uint32_t smb = smem_u32(smc);
    const uint32_t xab[2] = {smb + XA_B, smb + XA_B + 8192};
    const uint32_t wtb[2] = {smb + WT_B, smb + WT_B + 8192};
    const uint32_t w3b = smb + W3_B;

    const int tid = threadIdx.x, lane = tid & 31;
    const int g = lane >> 2, t = lane & 3;
    const int wid = tid >> 5, rg = wid >> 1, nh = wid & 1;
    const int wbase = rg << 5, nc0 = nh << 5;
    const int blk = blockIdx.x;

    const float* B1s[3] = {kb1, ab1, cb1};
    const float* B2s[3] = {kb2, ab2, cb2};
    const __half* xt = g_stile + ((size_t)blk << 14);
    const __half* at = g_atile + ((size_t)blk << 13);

    float acc[2][4][4], keyr = 0.f, agr[8], accr[8];
    #pragma unroll
    for (int o = 0; o < 8; o++) { accr[o] = 0.f; agr[o] = 0.f; }

    for (int k = 0; k < KKER; k++) {
        for (int net = 0; net < 3; net++) {
            const __half* wnet = g_wtile + (size_t)k * KSTR + (size_t)net * NOFF;
            const int NCH = (net == 2) ? 6 : 4;
            const __half* w2s = wnet + (size_t)NCH * 4096;
            const __half* w3s = w2s + 4096;

            cp_chunk(wtb[0], wnet, tid);
            cp_chunk(xab[0], xt, tid);
            CPA_COMMIT();
            if (tid < 64) {
                bs[tid]      = __ldg(B1s[net] + k * 64 + tid);
                bs[64 + tid] = __ldg(B2s[net] + k * 64 + tid);
            }
            zacc(acc);

            // ---- layer 1: NCH k64 chunks ----
            for (int j = 0; j < NCH; j++) {
                CPA_WAIT0();
                __syncthreads();
                if (j + 1 < NCH) {
                    const __half* xsrc = (j + 1 < 4) ? xt + ((j + 1) << 12)
                                                     : at + ((j - 3) << 12);
                    cp_chunk(wtb[(j + 1) & 1], wnet + ((size_t)(j + 1) << 12), tid);
                    cp_chunk(xab[(j + 1) & 1], xsrc, tid);
                } else {
                    cp_chunk(wtb[(j + 1) & 1], w2s, tid);
                    if (tid < 64) CPA16(w3b + (uint32_t)(tid << 4), w3s + (tid << 3));
                }
                CPA_COMMIT();
                mma_chunk(xa[j & 1], wt[j & 1], acc, wbase, nc0, g, t);
            }
            epi_h(acc, h, bs, wbase, nh, g, t);
            zacc(acc);

            // ---- layer 2 (single k64 chunk; A = h) ----
            CPA_WAIT0();
            __syncthreads();
            mma_chunk(h, wt[NCH & 1], acc, wbase, nc0, g, t);
            asm volatile("bar.sync %0, %1;" :: "r"(rg + 1), "r"(64) : "memory");
            epi_h(acc, h, bs + 64, wbase, nh, g, t);
            zacc(acc);
            asm volatile("bar.sync %0, %1;" :: "r"(rg + 1), "r"(64) : "memory");

            // ---- layer 3 (m32 x n8, nh==0 warps) ----
            if (nh == 0) {
                float a3[2][4];
                #pragma unroll
                for (int m = 0; m < 2; m++)
                    #pragma unroll
                    for (int i = 0; i < 4; i++) a3[m][i] = 0.f;
                #pragma unroll
                for (int q = 0; q < 4; q++) {
                    const __half* aq = h + (q << 10);
                    uint2 A00 = *reinterpret_cast<const uint2*>(aq + ((wbase + g) << 4) + 4 * t);
                    uint2 A01 = *reinterpret_cast<const uint2*>(aq + ((wbase + g + 8) << 4) + 4 * t);
                    uint2 A10 = *reinterpret_cast<const uint2*>(aq + ((wbase + g + 16) << 4) + 4 * t);
                    uint2 A11 = *reinterpret_cast<const uint2*>(aq + ((wbase + g + 24) << 4) + 4 * t);
                    uint2 Bv = *reinterpret_cast<const uint2*>(w3t + (q << 7) + (g << 4) + 4 * t);
                    mma16(a3[0], A00.x, A01.x, A00.y, A01.y, Bv.x, Bv.y);
                    mma16(a3[1], A10.x, A11.x, A10.y, A11.y, Bv.x, Bv.y);
                }
                #pragma unroll
                for (int mt = 0; mt < 2; mt++) {
                    int r0 = wbase + 16 * mt + g;
                    *reinterpret_cast<float2*>(ob + r0 * 10 + 2 * t)       = make_float2(a3[mt][0], a3[mt][1]);
                    *reinterpret_cast<float2*>(ob + (r0 + 8) * 10 + 2 * t) = make_float2(a3[mt][2], a3[mt][3]);
                }
            }
            __syncthreads();
            if (tid < 64) {
                const float* orow = ob + tid * 10;
                if (net == 0) {
                    keyr = fabsf(orow[0] + __ldg(kb3 + k)) + 1e-10f;
                } else if (net == 1) {
                    #pragma unroll
                    for (int o = 0; o < 8; o++)
                        agr[o] = sigf(orow[o] + __ldg(ab3 + k * 8 + o));
                } else {
                    #pragma unroll
                    for (int o = 0; o < 8; o++)
                        accr[o] += keyr * agr[o] * sigf(orow[o] + __ldg(cb3 + k * 8 + o));
                }
            }
        }
    }

    if (tid < 64) {
        float4* op = reinterpret_cast<float4*>(out + (size_t)(blk * TB + tid) * 8);
        op[0] = make_float4(accr[0], accr[1], accr[2], accr[3]);
        op[1] = make_float4(accr[4], accr[5], accr[6], accr[7]);
    }
}

extern "C" void kernel_launch(void* const* d_in, const int* in_sizes, int n_in,
                              void* d_out, int out_size)
{
    const float* states  = (const float*)d_in[0];
    const float* actions = (const float*)d_in[1];
    const float* kW1 = (const float*)d_in[2];  const float* kb1 = (const float*)d_in[3];
    const float* kW2 = (const float*)d_in[4];  const float* kb2 = (const float*)d_in[5];
    const float* kW3 = (const float*)d_in[6];  const float* kb3 = (const float*)d_in[7];
    const float* aW1 = (const float*)d_in[8];  const float* ab1 = (const float*)d_in[9];
    const float* aW2 = (const float*)d_in[10]; const float* ab2 = (const float*)d_in[11];
    const float* aW3 = (const float*)d_in[12]; const float* ab3 = (const float*)d_in[13];
    const float* cW1 = (const float*)d_in[14]; const float* cb1 = (const float*)d_in[15];
    const float* cW2 = (const float*)d_in[16]; const float* cb2 = (const float*)d_in[17];
    const float* cW3 = (const float*)d_in[18]; const float* cb3 = (const float*)d_in[19];
    float* out = (float*)d_out;

    prep_all<<<1144, 256>>>(states, actions,
                            kW1, kW2, kW3, aW1, aW2, aW3, cW1, cW2, cW3);

    cudaFuncSetAttribute(qplex_occ5_kernel,
                         cudaFuncAttributeMaxDynamicSharedMemorySize, (int)SMEMB);
    qplex_occ5_kernel<<<1024, NT, SMEMB>>>(
        kb1, kb2, kb3, ab1, ab2, ab3, cb1, cb2, cb3, out);
}